// round 1
// baseline (speedup 1.0000x reference)
#include <cuda_runtime.h>
#include <cstdint>

// Problem shape (fixed by the reference):
//   T = 2000 tags, V = 20000 videos, D = 768
//   E_POS = E_NEG = 100000
// Output layout: [cls_score (V*T f32), labels (V*T f32)]

#define D_DIM   768
#define T_DIM   2000

// ---------------------------------------------------------------------------
// Zero the whole output buffer (it is poisoned to 0xAA by the harness).
// float4 stores, exact mapping: one thread = one float4.
// ---------------------------------------------------------------------------
__global__ void zero_kernel(float4* __restrict__ out, long long nvec) {
    long long i = (long long)blockIdx.x * blockDim.x + threadIdx.x;
    if (i < nvec) {
        out[i] = make_float4(0.f, 0.f, 0.f, 0.f);
    }
}

// ---------------------------------------------------------------------------
// One warp per edge:
//   score = dot(h_tag[src], h_video[dst])  over D=768
//   atomicAdd(cls[dst*T + src], score)
//   if ADD_LABEL: atomicAdd(labels[dst*T + src], 1.0f)
// D=768 floats = 192 float4 = 6 float4 per lane.
// ---------------------------------------------------------------------------
template <bool ADD_LABEL>
__global__ void edge_dot_scatter_kernel(
    const float* __restrict__ h_tag,
    const float* __restrict__ h_video,
    const int*   __restrict__ src_idx,
    const int*   __restrict__ dst_idx,
    float*       __restrict__ cls,
    float*       __restrict__ labels,
    int nE)
{
    int warp = (blockIdx.x * blockDim.x + threadIdx.x) >> 5;
    int lane = threadIdx.x & 31;
    if (warp >= nE) return;

    int s = src_idx[warp];
    int d = dst_idx[warp];

    const float4* a = reinterpret_cast<const float4*>(h_tag   + (size_t)s * D_DIM);
    const float4* b = reinterpret_cast<const float4*>(h_video + (size_t)d * D_DIM);

    float acc = 0.f;
#pragma unroll
    for (int i = 0; i < D_DIM / (32 * 4); i++) {
        float4 va = a[lane + 32 * i];
        float4 vb = b[lane + 32 * i];
        acc += va.x * vb.x;
        acc += va.y * vb.y;
        acc += va.z * vb.z;
        acc += va.w * vb.w;
    }

    // butterfly reduce across the warp
#pragma unroll
    for (int off = 16; off > 0; off >>= 1)
        acc += __shfl_xor_sync(0xffffffffu, acc, off);

    if (lane == 0) {
        size_t cell = (size_t)d * T_DIM + (size_t)s;
        atomicAdd(&cls[cell], acc);
        if (ADD_LABEL) {
            atomicAdd(&labels[cell], 1.0f);
        }
    }
}

extern "C" void kernel_launch(void* const* d_in, const int* in_sizes, int n_in,
                              void* d_out, int out_size)
{
    const float* h_tag   = (const float*)d_in[0];
    const float* h_video = (const float*)d_in[1];
    const int*   pos_src = (const int*)d_in[2];
    const int*   pos_dst = (const int*)d_in[3];
    const int*   neg_src = (const int*)d_in[4];
    const int*   neg_dst = (const int*)d_in[5];

    const int nPos = in_sizes[2];
    const int nNeg = in_sizes[4];

    float* cls    = (float*)d_out;
    // V*T = out_size / 2 (cls_score first, then labels)
    long long vt  = (long long)out_size / 2;
    float* labels = cls + vt;

    // 1) zero the entire output (both matrices)
    {
        long long nvec = (long long)out_size / 4;   // out_size divisible by 4
        int  threads = 256;
        long long blocks = (nvec + threads - 1) / threads;
        zero_kernel<<<(unsigned)blocks, threads>>>((float4*)d_out, nvec);
    }

    // 2) positive edges: score + label
    {
        int threads = 256;                          // 8 warps / block
        int blocks  = (nPos * 32 + threads - 1) / threads;
        edge_dot_scatter_kernel<true><<<blocks, threads>>>(
            h_tag, h_video, pos_src, pos_dst, cls, labels, nPos);
    }

    // 3) negative edges: score only
    {
        int threads = 256;
        int blocks  = (nNeg * 32 + threads - 1) / threads;
        edge_dot_scatter_kernel<false><<<blocks, threads>>>(
            h_tag, h_video, neg_src, neg_dst, cls, labels, nNeg);
    }
}